// round 1
// baseline (speedup 1.0000x reference)
#include <cuda_runtime.h>
#include <math_constants.h>
#include <cstddef>

#define BB 4
#define CC 512
#define NTOK 1568
#define OQKV 1536
#define HH 8
#define DH 64
#define EPSV 1e-5f
#define SCL 0.125f   // 64^-0.5

// ---------------- scratch (allocation-free) ----------------
__device__ float g_xn  [BB * CC   * NTOK];   // normalized input  (b,c,n)
__device__ float g_qkv [BB * OQKV * NTOK];   // qkv projection    (b,o,n)
__device__ float g_ao  [BB * CC   * NTOK];   // attention output  (b,c,n)
__device__ float g_wqkv_t[CC * OQKV];        // w_qkv transposed  (c,o)
__device__ float g_wout_t[CC * CC];          // w_out transposed  (c,o)

// ---------------- weight transpose  W[O][C] -> Wt[C][O] ----------------
__global__ void transpose_kernel(const float* __restrict__ W,
                                 float* __restrict__ Wt, int O, int Cdim) {
    __shared__ float t[32][33];
    int o0 = blockIdx.x * 32, c0 = blockIdx.y * 32;
    int tx = threadIdx.x, ty = threadIdx.y;
    #pragma unroll
    for (int i = 0; i < 32; i += 8)
        t[ty + i][tx] = W[(size_t)(o0 + ty + i) * Cdim + c0 + tx];
    __syncthreads();
    #pragma unroll
    for (int i = 0; i < 32; i += 8)
        Wt[(size_t)(c0 + ty + i) * O + o0 + tx] = t[tx][ty + i];
}

// ---------------- LayerNorm over C per (b,n) ----------------
__global__ void ln_kernel(const float* __restrict__ x,
                          const float* __restrict__ w,
                          const float* __restrict__ bi,
                          float* __restrict__ xn) {
    int n = blockIdx.x * blockDim.x + threadIdx.x;
    int b = blockIdx.y;
    if (n >= NTOK) return;
    const float* xb = x + (size_t)b * CC * NTOK + n;
    float s = 0.f, s2 = 0.f;
    #pragma unroll 8
    for (int c = 0; c < CC; c++) {
        float v = xb[(size_t)c * NTOK];
        s += v; s2 += v * v;
    }
    float mean = s * (1.f / CC);
    float var  = fmaxf(s2 * (1.f / CC) - mean * mean, 0.f);
    float inv  = 1.f / (sqrtf(var) + EPSV);
    float* o = xn + (size_t)b * CC * NTOK + n;
    #pragma unroll 8
    for (int c = 0; c < CC; c++)
        o[(size_t)c * NTOK] = (xb[(size_t)c * NTOK] - mean) * inv * w[c] + bi[c];
}

// ---------------- GEMM: Y[b][o][n] = sum_c Wt[c][o] * X[b][c][n] (+bias) ----------------
// 64x64 tile, 16x16 threads, 4x4 micro-tile, k-tile 16. C fixed = 512.
__global__ __launch_bounds__(256) void gemm_kernel(
    const float* __restrict__ Wt, const float* __restrict__ X,
    const float* __restrict__ bias, float* __restrict__ Y, int O) {
    const int b  = blockIdx.z;
    const int n0 = blockIdx.x * 64, o0 = blockIdx.y * 64;
    __shared__ float Ws[16][64];
    __shared__ float Xs[16][64];
    const int tx = threadIdx.x, ty = threadIdx.y;
    const int tid = ty * 16 + tx;
    const float* Xb = X + (size_t)b * CC * NTOK;
    float acc[4][4] = {};
    for (int c0 = 0; c0 < CC; c0 += 16) {
        #pragma unroll
        for (int r = 0; r < 4; r++) {
            int e = tid + r * 256;
            int k = e >> 6, oo = e & 63;
            Ws[k][oo] = Wt[(size_t)(c0 + k) * O + o0 + oo];
        }
        #pragma unroll
        for (int r = 0; r < 4; r++) {
            int e = tid + r * 256;
            int k = e >> 6, nn = e & 63;
            int gn = n0 + nn;
            Xs[k][nn] = (gn < NTOK) ? Xb[(size_t)(c0 + k) * NTOK + gn] : 0.f;
        }
        __syncthreads();
        #pragma unroll
        for (int k = 0; k < 16; k++) {
            float a[4], xv[4];
            #pragma unroll
            for (int i = 0; i < 4; i++) a[i]  = Ws[k][ty + 16 * i];
            #pragma unroll
            for (int j = 0; j < 4; j++) xv[j] = Xs[k][tx + 16 * j];
            #pragma unroll
            for (int i = 0; i < 4; i++)
                #pragma unroll
                for (int j = 0; j < 4; j++)
                    acc[i][j] += a[i] * xv[j];
        }
        __syncthreads();
    }
    #pragma unroll
    for (int i = 0; i < 4; i++) {
        int oo = o0 + ty + 16 * i;
        float bv = bias ? bias[oo] : 0.f;
        #pragma unroll
        for (int j = 0; j < 4; j++) {
            int nn = n0 + tx + 16 * j;
            if (nn < NTOK)
                Y[((size_t)b * O + oo) * NTOK + nn] = acc[i][j] + bv;
        }
    }
}

// ---------------- flash attention, fp32, warp-per-query-row ----------------
// grid (49, H, B), block 1024 (32 warps). q tile 32, k tile 64.
__global__ __launch_bounds__(1024) void attn_kernel(const float* __restrict__ qkv,
                                                    float* __restrict__ out) {
    const int b = blockIdx.z, h = blockIdx.y, q0 = blockIdx.x * 32;
    const int warp = threadIdx.x >> 5, lane = threadIdx.x & 31;
    __shared__ float q_s[64][32];    // [d][m]
    __shared__ float k_s[64][64];    // [d][j]
    __shared__ float v_s[64][65];    // [j][d] padded

    const float* qb = qkv + ((size_t)b * OQKV + h * DH) * NTOK;
    const float* kb = qb + (size_t)(HH * DH) * NTOK;
    const float* vb = kb + (size_t)(HH * DH) * NTOK;

    for (int e = threadIdx.x; e < 64 * 32; e += 1024) {
        int d = e >> 5, m = e & 31;
        q_s[d][m] = qb[(size_t)d * NTOK + q0 + m] * SCL;
    }

    float m_i = -CUDART_INF_F, l_i = 0.f, acc0 = 0.f, acc1 = 0.f;
    const int d0 = lane, d1 = lane + 32;

    for (int j0 = 0; j0 < NTOK; j0 += 64) {
        __syncthreads();
        for (int e = threadIdx.x; e < 64 * 64; e += 1024) {
            int d = e >> 6, j = e & 63;
            int gj = j0 + j;
            bool ok = (gj < NTOK);
            k_s[d][j] = ok ? kb[(size_t)d * NTOK + gj] : 0.f;
            v_s[j][d] = ok ? vb[(size_t)d * NTOK + gj] : 0.f;
        }
        __syncthreads();

        float s0 = 0.f, s1 = 0.f;
        #pragma unroll
        for (int d = 0; d < 64; d++) {
            float qv = q_s[d][warp];
            s0 += qv * k_s[d][lane];
            s1 += qv * k_s[d][lane + 32];
        }
        if (j0 + lane >= NTOK)      s0 = -CUDART_INF_F;
        if (j0 + lane + 32 >= NTOK) s1 = -CUDART_INF_F;

        float tmax = fmaxf(s0, s1);
        #pragma unroll
        for (int off = 16; off; off >>= 1)
            tmax = fmaxf(tmax, __shfl_xor_sync(0xffffffffu, tmax, off));
        float m_new = fmaxf(m_i, tmax);
        float corr  = __expf(m_i - m_new);
        float p0 = __expf(s0 - m_new);
        float p1 = __expf(s1 - m_new);
        float psum = p0 + p1;
        #pragma unroll
        for (int off = 16; off; off >>= 1)
            psum += __shfl_xor_sync(0xffffffffu, psum, off);
        l_i = l_i * corr + psum;
        acc0 *= corr; acc1 *= corr;
        m_i = m_new;

        #pragma unroll
        for (int j = 0; j < 64; j++) {
            float pj = __shfl_sync(0xffffffffu, (j < 32) ? p0 : p1, j & 31);
            acc0 += pj * v_s[j][d0];
            acc1 += pj * v_s[j][d1];
        }
    }

    __syncthreads();
    float inv = 1.f / l_i;
    q_s[d0][warp] = acc0 * inv;
    q_s[d1][warp] = acc1 * inv;
    __syncthreads();

    float* ob = out + ((size_t)b * CC + h * DH) * NTOK;
    for (int e = threadIdx.x; e < 64 * 32; e += 1024) {
        int d = e >> 5, m = e & 31;
        ob[(size_t)d * NTOK + q0 + m] = q_s[d][m];
    }
}

// ---------------- launch ----------------
extern "C" void kernel_launch(void* const* d_in, const int* in_sizes, int n_in,
                              void* d_out, int out_size) {
    const float* x      = (const float*)d_in[0];
    const float* norm_w = (const float*)d_in[1];
    const float* norm_b = (const float*)d_in[2];
    const float* w_qkv  = (const float*)d_in[3];
    const float* w_out  = (const float*)d_in[4];
    const float* b_out  = (const float*)d_in[5];
    float* y = (float*)d_out;

    float *xn, *qkv, *ao, *wqkvt, *woutt;
    cudaGetSymbolAddress((void**)&xn,    g_xn);
    cudaGetSymbolAddress((void**)&qkv,   g_qkv);
    cudaGetSymbolAddress((void**)&ao,    g_ao);
    cudaGetSymbolAddress((void**)&wqkvt, g_wqkv_t);
    cudaGetSymbolAddress((void**)&woutt, g_wout_t);

    // weight transposes (cheap; done every call for determinism)
    transpose_kernel<<<dim3(OQKV / 32, CC / 32), dim3(32, 8)>>>(w_qkv, wqkvt, OQKV, CC);
    transpose_kernel<<<dim3(CC / 32,   CC / 32), dim3(32, 8)>>>(w_out, woutt, CC, CC);

    // layernorm
    ln_kernel<<<dim3((NTOK + 255) / 256, BB), 256>>>(x, norm_w, norm_b, xn);

    // qkv projection: O=1536
    gemm_kernel<<<dim3((NTOK + 63) / 64, OQKV / 64, BB), dim3(16, 16)>>>(
        wqkvt, xn, nullptr, qkv, OQKV);

    // attention
    attn_kernel<<<dim3(NTOK / 32, HH, BB), 1024>>>(qkv, ao);

    // output projection: O=512, + bias
    gemm_kernel<<<dim3((NTOK + 63) / 64, CC / 64, BB), dim3(16, 16)>>>(
        woutt, ao, b_out, y, CC);
}

// round 3
// speedup vs baseline: 2.2980x; 2.2980x over previous
#include <cuda_runtime.h>
#include <math_constants.h>
#include <cstddef>

#define BB 4
#define CC 512
#define NTOK 1568
#define NP 1664          // padded N (13 * 128)
#define OQKV 1536
#define HH 8
#define DH 64
#define EPSV 1e-5f
#define SCL 0.125f       // 64^-0.5

// attention dynamic smem layout (floats)
#define QS_OFF 0
#define KS_OFF (64 * 64)
#define VS_OFF (KS_OFF + 64 * 64)
#define PS_OFF (VS_OFF + 64 * 68)
#define ATTN_SMEM_FLOATS (PS_OFF + 64 * 64)
#define ATTN_SMEM_BYTES (ATTN_SMEM_FLOATS * 4)   // 66560

// ---------------- scratch (allocation-free) ----------------
__device__ float g_xn  [BB * CC   * NP];     // normalized input  (b,c,n) padded
__device__ float g_qkv [BB * OQKV * NP];     // qkv projection    (b,o,n) padded
__device__ float g_ao  [BB * CC   * NP];     // attention output  (b,c,n) padded
__device__ float g_wqkv_t[CC * OQKV];        // w_qkv transposed  (c,o)
__device__ float g_wout_t[CC * CC];          // w_out transposed  (c,o)

// ---------------- weight transpose  W[O][C] -> Wt[C][O] ----------------
__global__ void transpose_kernel(const float* __restrict__ W,
                                 float* __restrict__ Wt, int O, int Cdim) {
    __shared__ float t[32][33];
    int o0 = blockIdx.x * 32, c0 = blockIdx.y * 32;
    int tx = threadIdx.x, ty = threadIdx.y;
    #pragma unroll
    for (int i = 0; i < 32; i += 8)
        t[ty + i][tx] = W[(size_t)(o0 + ty + i) * Cdim + c0 + tx];
    __syncthreads();
    #pragma unroll
    for (int i = 0; i < 32; i += 8)
        Wt[(size_t)(c0 + ty + i) * O + o0 + tx] = t[tx][ty + i];
}

// ---------------- LayerNorm over C per (b,n), writes padded, zero pad ----------------
__global__ void ln_kernel(const float* __restrict__ x,
                          const float* __restrict__ w,
                          const float* __restrict__ bi,
                          float* __restrict__ xn) {
    int n = blockIdx.x * blockDim.x + threadIdx.x;
    int b = blockIdx.y;
    if (n >= NP) return;
    float* o = xn + (size_t)b * CC * NP + n;
    if (n >= NTOK) {
        for (int c = 0; c < CC; c++) o[(size_t)c * NP] = 0.f;
        return;
    }
    const float* xb = x + (size_t)b * CC * NTOK + n;
    float s = 0.f, s2 = 0.f;
    #pragma unroll 8
    for (int c = 0; c < CC; c++) {
        float v = xb[(size_t)c * NTOK];
        s += v; s2 += v * v;
    }
    float mean = s * (1.f / CC);
    float var  = fmaxf(s2 * (1.f / CC) - mean * mean, 0.f);
    float inv  = 1.f / (sqrtf(var) + EPSV);
    #pragma unroll 8
    for (int c = 0; c < CC; c++)
        o[(size_t)c * NP] = (xb[(size_t)c * NTOK] - mean) * inv * w[c] + bi[c];
}

// ---------------- GEMM: Y[b][o][n] = sum_c Wt[c][o] * X[b][c][n] (+bias) ----------------
// 128x128 tile, 256 threads, 8x8 microtile, BK=8. X padded to ldX; store guarded by Nmax.
__global__ __launch_bounds__(256, 2) void gemm_kernel(
    const float* __restrict__ Wt, const float* __restrict__ X,
    const float* __restrict__ bias, float* __restrict__ Y,
    int O, int ldX, int ldY, int Nmax) {
    const int b  = blockIdx.z;
    const int n0 = blockIdx.x * 128, o0 = blockIdx.y * 128;
    __shared__ float As[8][128];
    __shared__ float Bs[8][128];
    const int tid = threadIdx.x;
    const int lk = tid >> 5;            // 0..7
    const int lm = (tid & 31) * 4;      // 0..124
    const int ty = tid >> 4;            // 0..15
    const int tx = tid & 15;            // 0..15
    const int m = ty * 8, n = tx * 8;
    const float* Xb = X + (size_t)b * CC * ldX;
    float acc[8][8] = {};
    for (int c0 = 0; c0 < CC; c0 += 8) {
        *(float4*)&As[lk][lm] = *(const float4*)&Wt[(size_t)(c0 + lk) * O + o0 + lm];
        *(float4*)&Bs[lk][lm] = *(const float4*)&Xb[(size_t)(c0 + lk) * ldX + n0 + lm];
        __syncthreads();
        #pragma unroll
        for (int k = 0; k < 8; k++) {
            float4 a0 = *(float4*)&As[k][m];
            float4 a1 = *(float4*)&As[k][m + 4];
            float4 b0 = *(float4*)&Bs[k][n];
            float4 b1 = *(float4*)&Bs[k][n + 4];
            float av[8] = {a0.x, a0.y, a0.z, a0.w, a1.x, a1.y, a1.z, a1.w};
            float bv[8] = {b0.x, b0.y, b0.z, b0.w, b1.x, b1.y, b1.z, b1.w};
            #pragma unroll
            for (int i = 0; i < 8; i++)
                #pragma unroll
                for (int j = 0; j < 8; j++)
                    acc[i][j] += av[i] * bv[j];
        }
        __syncthreads();
    }
    #pragma unroll
    for (int i = 0; i < 8; i++) {
        int og = o0 + m + i;
        float bv = bias ? bias[og] : 0.f;
        float* yr = Y + ((size_t)b * O + og) * ldY;
        #pragma unroll
        for (int q = 0; q < 2; q++) {
            int ng = n0 + n + q * 4;
            if (ng + 3 < Nmax) {
                float4 v = make_float4(acc[i][q*4] + bv, acc[i][q*4+1] + bv,
                                       acc[i][q*4+2] + bv, acc[i][q*4+3] + bv);
                *(float4*)&yr[ng] = v;
            } else {
                #pragma unroll
                for (int e = 0; e < 4; e++)
                    if (ng + e < Nmax) yr[ng + e] = acc[i][q*4 + e] + bv;
            }
        }
    }
}

// ---------------- flash attention: 64q x 64k tiles, GEMM-GEMM, 256 threads ----------------
// grid (26, H, B). qkv padded (pad cols are zero). keys >= NTOK masked.
// Dynamic smem: Qs[64][64] | Ks[64][64] | Vs[64][68] | Ps[64][64]
__global__ __launch_bounds__(256) void attn_kernel(const float* __restrict__ qkv,
                                                   float* __restrict__ out) {
    extern __shared__ float sm[];
    float* Qs = sm + QS_OFF;   // [d][m] stride 64
    float* Ks = sm + KS_OFF;   // [d][j] stride 64
    float* Vs = sm + VS_OFF;   // [j][d] stride 68
    float* Ps = sm + PS_OFF;   // [m][j] stride 64

    const int b = blockIdx.z, h = blockIdx.y, q0 = blockIdx.x * 64;
    const int tid = threadIdx.x;
    const int ty = tid >> 4, tx = tid & 15;
    const int m0 = ty * 4;      // 4 query rows
    const int n0j = tx * 4;     // 4 key cols (S phase)
    const int d0 = tx * 4;      // 4 head-dim cols (PV phase)

    const float* qb = qkv + ((size_t)b * OQKV + h * DH) * NP;
    const float* kb = qb + (size_t)(HH * DH) * NP;
    const float* vb = kb + (size_t)(HH * DH) * NP;

    // load Q tile (scaled)
    for (int e = tid; e < 64 * 64; e += 256) {
        int d = e >> 6, mm = e & 63;
        Qs[d * 64 + mm] = qb[(size_t)d * NP + q0 + mm] * SCL;
    }

    float mrow[4], lrow[4], acc[4][4];
    #pragma unroll
    for (int i = 0; i < 4; i++) {
        mrow[i] = -CUDART_INF_F; lrow[i] = 0.f;
        #pragma unroll
        for (int j = 0; j < 4; j++) acc[i][j] = 0.f;
    }

    for (int j0 = 0; j0 < NTOK; j0 += 64) {
        __syncthreads();  // protect Ks/Vs/Ps from previous tile's readers
        for (int e = tid; e < 64 * 64; e += 256) {
            int d = e >> 6, j = e & 63;
            Ks[d * 64 + j] = kb[(size_t)d * NP + j0 + j];
            Vs[j * 68 + d] = vb[(size_t)d * NP + j0 + j];
        }
        __syncthreads();

        // S = Q^T K  (4x4 per thread)
        float s[4][4] = {};
        #pragma unroll
        for (int d = 0; d < 64; d++) {
            float4 a  = *(float4*)&Qs[d * 64 + m0];
            float4 kk = *(float4*)&Ks[d * 64 + n0j];
            float av[4] = {a.x, a.y, a.z, a.w};
            float kv[4] = {kk.x, kk.y, kk.z, kk.w};
            #pragma unroll
            for (int i = 0; i < 4; i++)
                #pragma unroll
                for (int j = 0; j < 4; j++)
                    s[i][j] += av[i] * kv[j];
        }
        // mask pad keys (only possible in the last tile)
        if (j0 + 64 > NTOK) {
            #pragma unroll
            for (int j = 0; j < 4; j++)
                if (j0 + n0j + j >= NTOK) {
                    #pragma unroll
                    for (int i = 0; i < 4; i++) s[i][j] = -CUDART_INF_F;
                }
        }

        // online softmax per row; P -> smem
        #pragma unroll
        for (int i = 0; i < 4; i++) {
            float rmax = fmaxf(fmaxf(s[i][0], s[i][1]), fmaxf(s[i][2], s[i][3]));
            #pragma unroll
            for (int off = 1; off < 16; off <<= 1)
                rmax = fmaxf(rmax, __shfl_xor_sync(0xffffffffu, rmax, off));
            float mn = fmaxf(mrow[i], rmax);
            float corr = __expf(mrow[i] - mn);
            mrow[i] = mn;
            float p0 = __expf(s[i][0] - mn);
            float p1 = __expf(s[i][1] - mn);
            float p2 = __expf(s[i][2] - mn);
            float p3 = __expf(s[i][3] - mn);
            float rsum = p0 + p1 + p2 + p3;
            #pragma unroll
            for (int off = 1; off < 16; off <<= 1)
                rsum += __shfl_xor_sync(0xffffffffu, rsum, off);
            lrow[i] = lrow[i] * corr + rsum;
            #pragma unroll
            for (int j = 0; j < 4; j++) acc[i][j] *= corr;
            *(float4*)&Ps[(m0 + i) * 64 + n0j] = make_float4(p0, p1, p2, p3);
        }
        __syncthreads();

        // O += P V   (reduction over j, 4 j per step)
        #pragma unroll
        for (int j4 = 0; j4 < 16; j4++) {
            float4 v0 = *(float4*)&Vs[(j4 * 4 + 0) * 68 + d0];
            float4 v1 = *(float4*)&Vs[(j4 * 4 + 1) * 68 + d0];
            float4 v2 = *(float4*)&Vs[(j4 * 4 + 2) * 68 + d0];
            float4 v3 = *(float4*)&Vs[(j4 * 4 + 3) * 68 + d0];
            #pragma unroll
            for (int i = 0; i < 4; i++) {
                float4 p = *(float4*)&Ps[(m0 + i) * 64 + j4 * 4];
                acc[i][0] += p.x * v0.x + p.y * v1.x + p.z * v2.x + p.w * v3.x;
                acc[i][1] += p.x * v0.y + p.y * v1.y + p.z * v2.y + p.w * v3.y;
                acc[i][2] += p.x * v0.z + p.y * v1.z + p.z * v2.z + p.w * v3.z;
                acc[i][3] += p.x * v0.w + p.y * v1.w + p.z * v2.w + p.w * v3.w;
            }
        }
    }

    // normalize, stage to smem (reuse Qs as [d][m]), coalesced write
    __syncthreads();
    #pragma unroll
    for (int i = 0; i < 4; i++) {
        float inv = 1.f / lrow[i];
        #pragma unroll
        for (int dd = 0; dd < 4; dd++)
            Qs[(d0 + dd) * 64 + m0 + i] = acc[i][dd] * inv;
    }
    __syncthreads();
    float* ob = out + ((size_t)b * CC + h * DH) * NP;
    for (int e = tid; e < 64 * 64; e += 256) {
        int d = e >> 6, mm = e & 63;
        ob[(size_t)d * NP + q0 + mm] = Qs[d * 64 + mm];
    }
}

// ---------------- launch ----------------
extern "C" void kernel_launch(void* const* d_in, const int* in_sizes, int n_in,
                              void* d_out, int out_size) {
    const float* x      = (const float*)d_in[0];
    const float* norm_w = (const float*)d_in[1];
    const float* norm_b = (const float*)d_in[2];
    const float* w_qkv  = (const float*)d_in[3];
    const float* w_out  = (const float*)d_in[4];
    const float* b_out  = (const float*)d_in[5];
    float* y = (float*)d_out;

    float *xn, *qkv, *ao, *wqkvt, *woutt;
    cudaGetSymbolAddress((void**)&xn,    g_xn);
    cudaGetSymbolAddress((void**)&qkv,   g_qkv);
    cudaGetSymbolAddress((void**)&ao,    g_ao);
    cudaGetSymbolAddress((void**)&wqkvt, g_wqkv_t);
    cudaGetSymbolAddress((void**)&woutt, g_wout_t);

    cudaFuncSetAttribute(attn_kernel, cudaFuncAttributeMaxDynamicSharedMemorySize,
                         ATTN_SMEM_BYTES);

    transpose_kernel<<<dim3(OQKV / 32, CC / 32), dim3(32, 8)>>>(w_qkv, wqkvt, OQKV, CC);
    transpose_kernel<<<dim3(CC / 32,   CC / 32), dim3(32, 8)>>>(w_out, woutt, CC, CC);

    ln_kernel<<<dim3((NP + 255) / 256, BB), 256>>>(x, norm_w, norm_b, xn);

    // QKV projection: O=1536, padded in/out, no bias
    gemm_kernel<<<dim3(NP / 128, OQKV / 128, BB), 256>>>(
        wqkvt, xn, nullptr, qkv, OQKV, NP, NP, NP);

    // attention (26 q-tiles cover all padded queries; pad queries are harmless)
    attn_kernel<<<dim3(NP / 64, HH, BB), 256, ATTN_SMEM_BYTES>>>(qkv, ao);

    // output projection: O=512, + bias, store guarded to unpadded y
    gemm_kernel<<<dim3(NP / 128, CC / 128, BB), 256>>>(
        woutt, ao, b_out, y, CC, NP, NTOK, NTOK);
}

// round 5
// speedup vs baseline: 4.7905x; 2.0846x over previous
#include <cuda_runtime.h>
#include <math_constants.h>
#include <cstdint>
#include <cstddef>

#define BB 4
#define CC 512
#define NTOK 1568
#define NP 1664          // padded N (13 * 128)
#define OQKV 1536
#define HH 8
#define DH 64
#define EPSV 1e-5f
#define SCL 0.125f       // 64^-0.5

// ---------------- scratch (allocation-free) ----------------
__device__ float g_xn  [BB * CC   * NP];     // normalized input  (b,c,n) padded
__device__ float g_qkv [BB * OQKV * NP];     // qkv projection    (b,o,n) padded
__device__ float g_ao  [BB * CC   * NP];     // attention output  (b,c,n) padded

// ---------------- helpers ----------------
__device__ __forceinline__ float tf32r(float x) {
    uint32_t y;
    asm("cvt.rna.tf32.f32 %0, %1;" : "=r"(y) : "f"(x));
    return __uint_as_float(y);
}
__device__ __forceinline__ void mma_tf32(float* c, uint32_t a0, uint32_t a1,
                                         uint32_t a2, uint32_t a3,
                                         uint32_t b0, uint32_t b1) {
    asm volatile(
        "mma.sync.aligned.m16n8k8.row.col.f32.tf32.tf32.f32 "
        "{%0,%1,%2,%3}, {%4,%5,%6,%7}, {%8,%9}, {%0,%1,%2,%3};\n"
        : "+f"(c[0]), "+f"(c[1]), "+f"(c[2]), "+f"(c[3])
        : "r"(a0), "r"(a1), "r"(a2), "r"(a3), "r"(b0), "r"(b1));
}

// ---------------- LayerNorm over C per (b,n), writes padded, zero pad ----------------
__global__ void ln_kernel(const float* __restrict__ x,
                          const float* __restrict__ w,
                          const float* __restrict__ bi,
                          float* __restrict__ xn) {
    int n = blockIdx.x * blockDim.x + threadIdx.x;
    int b = blockIdx.y;
    if (n >= NP) return;
    float* o = xn + (size_t)b * CC * NP + n;
    if (n >= NTOK) {
        for (int c = 0; c < CC; c++) o[(size_t)c * NP] = 0.f;
        return;
    }
    const float* xb = x + (size_t)b * CC * NTOK + n;
    float s = 0.f, s2 = 0.f;
    #pragma unroll 8
    for (int c = 0; c < CC; c++) {
        float v = xb[(size_t)c * NTOK];
        s += v; s2 += v * v;
    }
    float mean = s * (1.f / CC);
    float var  = fmaxf(s2 * (1.f / CC) - mean * mean, 0.f);
    float inv  = 1.f / (sqrtf(var) + EPSV);
    #pragma unroll 8
    for (int c = 0; c < CC; c++)
        o[(size_t)c * NP] = (xb[(size_t)c * NTOK] - mean) * inv * w[c] + bi[c];
}

// ---------------- tensor-core GEMM: Y[b][o][n] = sum_c W[o][c] X[b][c][n] (+bias) ----
// block 128(o) x 128(n) x BK=32, 8 warps, warp tile 32x64, mma m16n8k8 tf32.
__global__ __launch_bounds__(256) void gemm_tc(
    const float* __restrict__ W, const float* __restrict__ X,
    const float* __restrict__ bias, float* __restrict__ Y,
    int O, int ldX, int ldY, int Nmax) {
    __shared__ float As[128 * 36];   // [m][k] pad-36 -> conflict-free frag loads
    __shared__ float Bs[32 * 136];   // [k][n] pad-136

    const int b  = blockIdx.z;
    const int n0 = blockIdx.x * 128, o0 = blockIdx.y * 128;
    const int tid = threadIdx.x;
    const int warp = tid >> 5, lane = tid & 31;
    const int wm = warp >> 1, wn = warp & 1;
    const int g = lane >> 2, t = lane & 3;
    const float* Xb = X + (size_t)b * CC * ldX;

    float acc[2][8][4] = {};

    for (int c0 = 0; c0 < CC; c0 += 32) {
        // load A tile (128x32) from W[o][c], row-major, cvt to tf32
        #pragma unroll
        for (int i = 0; i < 4; i++) {
            int f4 = tid + i * 256;
            int r = f4 >> 3, c4 = (f4 & 7) << 2;
            float4 v = *(const float4*)&W[(size_t)(o0 + r) * CC + c0 + c4];
            float* d = &As[r * 36 + c4];
            d[0] = tf32r(v.x); d[1] = tf32r(v.y); d[2] = tf32r(v.z); d[3] = tf32r(v.w);
        }
        // load B tile (32x128) from X[c][n]
        #pragma unroll
        for (int i = 0; i < 4; i++) {
            int f4 = tid + i * 256;
            int r = f4 >> 5, c4 = (f4 & 31) << 2;
            float4 v = *(const float4*)&Xb[(size_t)(c0 + r) * ldX + n0 + c4];
            *(float4*)&Bs[r * 136 + c4] =
                make_float4(tf32r(v.x), tf32r(v.y), tf32r(v.z), tf32r(v.w));
        }
        __syncthreads();
        #pragma unroll
        for (int ks = 0; ks < 4; ks++) {
            int k0 = ks * 8;
            uint32_t a[2][4];
            #pragma unroll
            for (int mi = 0; mi < 2; mi++) {
                int m = wm * 32 + mi * 16 + g;
                a[mi][0] = __float_as_uint(As[m * 36 + k0 + t]);
                a[mi][1] = __float_as_uint(As[(m + 8) * 36 + k0 + t]);
                a[mi][2] = __float_as_uint(As[m * 36 + k0 + t + 4]);
                a[mi][3] = __float_as_uint(As[(m + 8) * 36 + k0 + t + 4]);
            }
            #pragma unroll
            for (int ni = 0; ni < 8; ni++) {
                int n = wn * 64 + ni * 8 + g;
                uint32_t b0 = __float_as_uint(Bs[(k0 + t) * 136 + n]);
                uint32_t b1 = __float_as_uint(Bs[(k0 + t + 4) * 136 + n]);
                mma_tf32(acc[0][ni], a[0][0], a[0][1], a[0][2], a[0][3], b0, b1);
                mma_tf32(acc[1][ni], a[1][0], a[1][1], a[1][2], a[1][3], b0, b1);
            }
        }
        __syncthreads();
    }

    // epilogue
    #pragma unroll
    for (int mi = 0; mi < 2; mi++) {
        int o_r = o0 + wm * 32 + mi * 16 + g;
        float bv0 = bias ? bias[o_r]     : 0.f;
        float bv1 = bias ? bias[o_r + 8] : 0.f;
        float* y0 = Y + ((size_t)b * O + o_r) * ldY;
        float* y1 = y0 + (size_t)8 * ldY;
        #pragma unroll
        for (int ni = 0; ni < 8; ni++) {
            int n = n0 + wn * 64 + ni * 8 + 2 * t;
            if (n + 1 < Nmax) {
                *(float2*)&y0[n] = make_float2(acc[mi][ni][0] + bv0, acc[mi][ni][1] + bv0);
                *(float2*)&y1[n] = make_float2(acc[mi][ni][2] + bv1, acc[mi][ni][3] + bv1);
            } else if (n < Nmax) {
                y0[n] = acc[mi][ni][0] + bv0;
                y1[n] = acc[mi][ni][2] + bv1;
            }
        }
    }
}

// ---------------- tensor-core flash attention: 64q x 64k tiles ----------------
// dyn smem: Qs[64][68] Ks[64][68] Vs[64][68] Ps[64][68] mS[64] lS[64] corrS[64]
#define AQS 0
#define AKS (64 * 68)
#define AVS (2 * 64 * 68)
#define APS (3 * 64 * 68)
#define AMS (4 * 64 * 68)
#define ALS (AMS + 64)
#define ACS (ALS + 64)
#define ATTN_SMEM_BYTES ((ACS + 64) * 4)

__global__ __launch_bounds__(256) void attn_tc(const float* __restrict__ qkv,
                                               float* __restrict__ out) {
    extern __shared__ float sm[];
    float* Qs = sm + AQS;   // [m][d] stride 68
    float* Ks = sm + AKS;   // [j][d] stride 68
    float* Vs = sm + AVS;   // [d][j] stride 68
    float* Ps = sm + APS;   // [m][j] stride 68
    float* mS = sm + AMS;
    float* lS = sm + ALS;
    float* cS = sm + ACS;

    const int b = blockIdx.z, h = blockIdx.y, q0 = blockIdx.x * 64;
    const int tid = threadIdx.x;
    const int warp = tid >> 5, lane = tid & 31;
    const int wm = warp >> 1, wn = warp & 1;      // wm: 0..3 (16 rows), wn: 0..1 (32 cols)
    const int g = lane >> 2, t = lane & 3;

    const float* qb = qkv + ((size_t)b * OQKV + h * DH) * NP;
    const float* kb = qb + (size_t)(HH * DH) * NP;
    const float* vb = kb + (size_t)(HH * DH) * NP;

    if (tid < 64) { mS[tid] = -CUDART_INF_F; lS[tid] = 0.f; }
    // load Q [m][d], scaled + tf32
    for (int e = tid; e < 64 * 64; e += 256) {
        int m = e & 63, d = e >> 6;
        Qs[m * 68 + d] = tf32r(qb[(size_t)d * NP + q0 + m] * SCL);
    }
    __syncthreads();

    float oacc[4][4] = {};   // 16m x 32d warp tile: 4 mma accums

    for (int j0 = 0; j0 < NTOK; j0 += 64) {
        __syncthreads();   // prev-tile readers of Ks/Vs/Ps done
        // K transpose-on-load [j][d]; V natural [d][j]
        for (int e = tid; e < 64 * 64; e += 256) {
            int j = e & 63, d = e >> 6;
            Ks[j * 68 + d] = tf32r(kb[(size_t)d * NP + j0 + j]);
        }
        #pragma unroll
        for (int i = 0; i < 4; i++) {
            int f4 = tid + i * 256;
            int d = f4 >> 4, j4 = (f4 & 15) << 2;
            float4 v = *(const float4*)&vb[(size_t)d * NP + j0 + j4];
            *(float4*)&Vs[d * 68 + j4] =
                make_float4(tf32r(v.x), tf32r(v.y), tf32r(v.z), tf32r(v.w));
        }
        __syncthreads();

        // S = Q K^T : warp computes 16m x 32j
        float sacc[4][4] = {};
        #pragma unroll
        for (int ks = 0; ks < 8; ks++) {
            int k0 = ks * 8;
            int m = wm * 16 + g;
            uint32_t a0 = __float_as_uint(Qs[m * 68 + k0 + t]);
            uint32_t a1 = __float_as_uint(Qs[(m + 8) * 68 + k0 + t]);
            uint32_t a2 = __float_as_uint(Qs[m * 68 + k0 + t + 4]);
            uint32_t a3 = __float_as_uint(Qs[(m + 8) * 68 + k0 + t + 4]);
            #pragma unroll
            for (int ni = 0; ni < 4; ni++) {
                int j = wn * 32 + ni * 8 + g;
                uint32_t b0 = __float_as_uint(Ks[j * 68 + k0 + t]);
                uint32_t b1 = __float_as_uint(Ks[j * 68 + k0 + t + 4]);
                mma_tf32(sacc[ni], a0, a1, a2, a3, b0, b1);
            }
        }
        // S frags -> Ps
        #pragma unroll
        for (int ni = 0; ni < 4; ni++) {
            int col = wn * 32 + ni * 8 + 2 * t;
            int r0 = wm * 16 + g;
            *(float2*)&Ps[r0 * 68 + col]       = make_float2(sacc[ni][0], sacc[ni][1]);
            *(float2*)&Ps[(r0 + 8) * 68 + col] = make_float2(sacc[ni][2], sacc[ni][3]);
        }
        __syncthreads();

        // online softmax: 4 threads per row, 16 cols each
        {
            int row = tid >> 2, sub = tid & 3;
            int cbase = sub * 16;
            float4 pv[4];
            float mx = -CUDART_INF_F;
            #pragma unroll
            for (int i = 0; i < 4; i++) {
                pv[i] = *(float4*)&Ps[row * 68 + cbase + i * 4];
                mx = fmaxf(mx, fmaxf(fmaxf(pv[i].x, pv[i].y), fmaxf(pv[i].z, pv[i].w)));
            }
            mx = fmaxf(mx, __shfl_xor_sync(0xffffffffu, mx, 1));
            mx = fmaxf(mx, __shfl_xor_sync(0xffffffffu, mx, 2));
            float mold = mS[row];
            float mnew = fmaxf(mold, mx);
            float sum = 0.f;
            #pragma unroll
            for (int i = 0; i < 4; i++) {
                int jg = j0 + cbase + i * 4;
                float e0 = (jg + 0 < NTOK) ? __expf(pv[i].x - mnew) : 0.f;
                float e1 = (jg + 1 < NTOK) ? __expf(pv[i].y - mnew) : 0.f;
                float e2 = (jg + 2 < NTOK) ? __expf(pv[i].z - mnew) : 0.f;
                float e3 = (jg + 3 < NTOK) ? __expf(pv[i].w - mnew) : 0.f;
                sum += (e0 + e1) + (e2 + e3);
                *(float4*)&Ps[row * 68 + cbase + i * 4] =
                    make_float4(tf32r(e0), tf32r(e1), tf32r(e2), tf32r(e3));
            }
            sum += __shfl_xor_sync(0xffffffffu, sum, 1);
            sum += __shfl_xor_sync(0xffffffffu, sum, 2);
            if (sub == 0) {
                float corr = __expf(mold - mnew);
                cS[row] = corr;
                lS[row] = lS[row] * corr + sum;
                mS[row] = mnew;
            }
        }
        __syncthreads();

        // rescale O, then O += P V  (warp: 16m x 32d)
        float c0r = cS[wm * 16 + g];
        float c1r = cS[wm * 16 + g + 8];
        #pragma unroll
        for (int ni = 0; ni < 4; ni++) {
            oacc[ni][0] *= c0r; oacc[ni][1] *= c0r;
            oacc[ni][2] *= c1r; oacc[ni][3] *= c1r;
        }
        #pragma unroll
        for (int ks = 0; ks < 8; ks++) {
            int k0 = ks * 8;
            int m = wm * 16 + g;
            uint32_t a0 = __float_as_uint(Ps[m * 68 + k0 + t]);
            uint32_t a1 = __float_as_uint(Ps[(m + 8) * 68 + k0 + t]);
            uint32_t a2 = __float_as_uint(Ps[m * 68 + k0 + t + 4]);
            uint32_t a3 = __float_as_uint(Ps[(m + 8) * 68 + k0 + t + 4]);
            #pragma unroll
            for (int ni = 0; ni < 4; ni++) {
                int d = wn * 32 + ni * 8 + g;
                uint32_t b0 = __float_as_uint(Vs[d * 68 + k0 + t]);
                uint32_t b1 = __float_as_uint(Vs[d * 68 + k0 + t + 4]);
                mma_tf32(oacc[ni], a0, a1, a2, a3, b0, b1);
            }
        }
    }

    // normalize, stage [d][m] in Ks, coalesced store
    __syncthreads();
    if (tid < 64) cS[tid] = 1.f / lS[tid];
    __syncthreads();
    {
        float i0 = cS[wm * 16 + g];
        float i1 = cS[wm * 16 + g + 8];
        #pragma unroll
        for (int ni = 0; ni < 4; ni++) {
            int d = wn * 32 + ni * 8 + 2 * t;
            int m = wm * 16 + g;
            Ks[d * 68 + m]           = oacc[ni][0] * i0;
            Ks[(d + 1) * 68 + m]     = oacc[ni][1] * i0;
            Ks[d * 68 + m + 8]       = oacc[ni][2] * i1;
            Ks[(d + 1) * 68 + m + 8] = oacc[ni][3] * i1;
        }
    }
    __syncthreads();
    float* ob = out + ((size_t)b * CC + h * DH) * NP;
    for (int e = tid; e < 64 * 64; e += 256) {
        int m = e & 63, d = e >> 6;
        ob[(size_t)d * NP + q0 + m] = Ks[d * 68 + m];
    }
}

// ---------------- launch ----------------
extern "C" void kernel_launch(void* const* d_in, const int* in_sizes, int n_in,
                              void* d_out, int out_size) {
    const float* x      = (const float*)d_in[0];
    const float* norm_w = (const float*)d_in[1];
    const float* norm_b = (const float*)d_in[2];
    const float* w_qkv  = (const float*)d_in[3];
    const float* w_out  = (const float*)d_in[4];
    const float* b_out  = (const float*)d_in[5];
    float* y = (float*)d_out;

    float *xn, *qkv, *ao;
    cudaGetSymbolAddress((void**)&xn,  g_xn);
    cudaGetSymbolAddress((void**)&qkv, g_qkv);
    cudaGetSymbolAddress((void**)&ao,  g_ao);

    cudaFuncSetAttribute(attn_tc, cudaFuncAttributeMaxDynamicSharedMemorySize,
                         ATTN_SMEM_BYTES);

    ln_kernel<<<dim3((NP + 255) / 256, BB), 256>>>(x, norm_w, norm_b, xn);

    // QKV projection: O=1536 (W used natively [o][c])
    gemm_tc<<<dim3(NP / 128, OQKV / 128, BB), 256>>>(
        w_qkv, xn, nullptr, qkv, OQKV, NP, NP, NP);

    // attention
    attn_tc<<<dim3(NP / 64, HH, BB), 256, ATTN_SMEM_BYTES>>>(qkv, ao);

    // output projection: O=512, + bias, store guarded to unpadded y
    gemm_tc<<<dim3(NP / 128, CC / 128, BB), 256>>>(
        w_out, ao, b_out, y, CC, NP, NTOK, NTOK);
}